// round 4
// baseline (speedup 1.0000x reference)
#include <cuda_runtime.h>

// Problem constants (fixed by the dataset)
#define NN      100000      // nodes
#define DIN     256         // input feature dim
#define DOUT    32          // output feature dim
#define KC      32          // K-chunk (floats) per pipeline stage
#define NCHUNK  (DIN / KC)  // 8 stages
#define RPB     256         // rows per GEMM block
#define GTHREADS 256

// Scratch for pre_sup = x @ W  [NN, DOUT] (12.8 MB, device global per rules)
__device__ float g_presup[(size_t)NN * DOUT];

typedef unsigned long long ull;

__device__ __forceinline__ void ffma2(ull& d, ull a, ull b) {
    asm volatile("fma.rn.f32x2 %0, %1, %2, %0;" : "+l"(d) : "l"(a), "l"(b));
}
__device__ __forceinline__ ull pack2(float x) {
    ull r; asm("mov.b64 %0, {%1, %1};" : "=l"(r) : "f"(x)); return r;
}
__device__ __forceinline__ void unpack2(ull v, float& lo, float& hi) {
    asm("mov.b64 {%0, %1}, %2;" : "=f"(lo), "=f"(hi) : "l"(v));
}

// ---------------------------------------------------------------------------
// Kernel 1: GEMM  pre_sup[N, 32] = x[N, 256] @ W[256, 32]
// 256 threads/block covering 256 rows x 32 cols. Thread tile 4 rows x 8 cols
// as 4x4 packed f32x2 accumulators (FFMA2).
// Software pipeline: W staged to smem once; X tile double-buffered k-major
// (Xs[k][row] -> bank = row: conflict-free STS and 8-bank/4-way-bcast LDS).
// One __syncthreads per K-chunk; LDG of chunk c+2 overlaps compute of chunk c.
// Dynamic smem: 32KB W + 2x32KB X = 96KB.
// ---------------------------------------------------------------------------
__global__ __launch_bounds__(GTHREADS, 2) void gemm_kernel(const float* __restrict__ x,
                                                           const float* __restrict__ w) {
    extern __shared__ float smem[];
    float* Ws = smem;                  // [256][32]  = 8192 floats (32 KB)
    float* Xs = smem + DIN * DOUT;     // [2][KC][RPB] = 16384 floats (64 KB)

    const int tid  = threadIdx.x;
    const int row0 = blockIdx.x * RPB;
    const int tc   = tid & 3;    // -> cols  tc*8 .. tc*8+7
    const int tr   = tid >> 2;   // -> rows  tr*4 .. tr*4+3

    const int  myrow = row0 + tid;
    const bool rowok = (myrow < NN);
    const float* xrow = x + (size_t)myrow * DIN;
    const float4 f0 = make_float4(0.f, 0.f, 0.f, 0.f);

    // ---- Prologue: stage full W, chunk0 -> buf0, issue LDG for chunk1 ----
#pragma unroll
    for (int i = 0; i < 8; i++) {
        float4 wv = ((const float4*)w)[tid + i * GTHREADS];
        ((float4*)Ws)[tid + i * GTHREADS] = wv;
    }
    float4 xreg[8];
#pragma unroll
    for (int i = 0; i < 8; i++)
        xreg[i] = rowok ? *(const float4*)(xrow + i * 4) : f0;
#pragma unroll
    for (int i = 0; i < 8; i++) {       // transpose-store chunk0 into buf0
        Xs[(i * 4 + 0) * RPB + tid] = xreg[i].x;
        Xs[(i * 4 + 1) * RPB + tid] = xreg[i].y;
        Xs[(i * 4 + 2) * RPB + tid] = xreg[i].z;
        Xs[(i * 4 + 3) * RPB + tid] = xreg[i].w;
    }
#pragma unroll
    for (int i = 0; i < 8; i++)         // prefetch chunk1
        xreg[i] = rowok ? *(const float4*)(xrow + KC + i * 4) : f0;
    __syncthreads();

    ull acc[4][4];
#pragma unroll
    for (int r = 0; r < 4; r++)
#pragma unroll
        for (int c = 0; c < 4; c++) acc[r][c] = 0ULL;

    // ---- Mainloop over 8 K-chunks ----
    for (int c = 0; c < NCHUNK; c++) {
        const float* Xb = Xs + (c & 1) * (KC * RPB);
        const float* Wc = Ws + c * (KC * DOUT);

#pragma unroll 8
        for (int k = 0; k < KC; k++) {
            const float* wrow = Wc + k * DOUT + tc * 8;
            ull w0 = *(const ull*)(wrow + 0);
            ull w1 = *(const ull*)(wrow + 2);
            ull w2 = *(const ull*)(wrow + 4);
            ull w3 = *(const ull*)(wrow + 6);
            const float* xk = Xb + k * RPB + tr * 4;
#pragma unroll
            for (int r = 0; r < 4; r++) {
                ull xv = pack2(xk[r]);
                ffma2(acc[r][0], xv, w0);
                ffma2(acc[r][1], xv, w1);
                ffma2(acc[r][2], xv, w2);
                ffma2(acc[r][3], xv, w3);
            }
        }

        if (c + 1 < NCHUNK) {
            // Store prefetched chunk c+1 into the idle buffer (readers of its
            // previous contents finished before the last __syncthreads).
            float* Xn = Xs + ((c + 1) & 1) * (KC * RPB);
#pragma unroll
            for (int i = 0; i < 8; i++) {
                Xn[(i * 4 + 0) * RPB + tid] = xreg[i].x;
                Xn[(i * 4 + 1) * RPB + tid] = xreg[i].y;
                Xn[(i * 4 + 2) * RPB + tid] = xreg[i].z;
                Xn[(i * 4 + 3) * RPB + tid] = xreg[i].w;
            }
            if (c + 2 < NCHUNK) {        // prefetch chunk c+2
#pragma unroll
                for (int i = 0; i < 8; i++)
                    xreg[i] = rowok ? *(const float4*)(xrow + (c + 2) * KC + i * 4) : f0;
            }
            __syncthreads();
        }
    }

    // ---- Epilogue: unpack and store two float4 per row ----
#pragma unroll
    for (int r = 0; r < 4; r++) {
        int grow = row0 + tr * 4 + r;
        if (grow < NN) {
            float4 o0, o1;
            unpack2(acc[r][0], o0.x, o0.y);
            unpack2(acc[r][1], o0.z, o0.w);
            unpack2(acc[r][2], o1.x, o1.y);
            unpack2(acc[r][3], o1.z, o1.w);
            float* dst = g_presup + (size_t)grow * DOUT + tc * 8;
            *(float4*)(dst + 0) = o0;
            *(float4*)(dst + 4) = o1;
        }
    }
}

// ---------------------------------------------------------------------------
// Kernel 2: Scatter SpMM  out[row[e]] += val[e] * pre_sup[col[e]]
// 8 threads per edge; one float4 gather + one red.global.add.v4.f32 each.
// ---------------------------------------------------------------------------
__global__ __launch_bounds__(256) void scatter_kernel(const int*   __restrict__ arow,
                                                      const int*   __restrict__ acol,
                                                      const float* __restrict__ aval,
                                                      float*       __restrict__ out,
                                                      int n_edges) {
    long long g = (long long)blockIdx.x * blockDim.x + threadIdx.x;
    int e    = (int)(g >> 3);
    int part = (int)(g & 7);
    if (e >= n_edges) return;

    int   r = arow[e];
    int   c = acol[e];
    float v = aval[e];

    float4 p = *(const float4*)(g_presup + (size_t)c * DOUT + part * 4);
    float m0 = v * p.x, m1 = v * p.y, m2 = v * p.z, m3 = v * p.w;

    float* dst = out + (size_t)r * DOUT + part * 4;
    asm volatile("red.global.add.v4.f32 [%0], {%1, %2, %3, %4};"
                 :: "l"(dst), "f"(m0), "f"(m1), "f"(m2), "f"(m3)
                 : "memory");
}

// ---------------------------------------------------------------------------
// Kernel 3: in-place ReLU on out
// ---------------------------------------------------------------------------
__global__ __launch_bounds__(256) void relu_kernel(float* __restrict__ out, int n4) {
    int i = blockIdx.x * blockDim.x + threadIdx.x;
    if (i < n4) {
        float4 v = ((float4*)out)[i];
        v.x = fmaxf(v.x, 0.f);
        v.y = fmaxf(v.y, 0.f);
        v.z = fmaxf(v.z, 0.f);
        v.w = fmaxf(v.w, 0.f);
        ((float4*)out)[i] = v;
    }
}

// ---------------------------------------------------------------------------
// kernel_launch: memset(out) -> gemm -> scatter -> relu
// ---------------------------------------------------------------------------
extern "C" void kernel_launch(void* const* d_in, const int* in_sizes, int n_in,
                              void* d_out, int out_size) {
    const float* x    = (const float*)d_in[0];
    const int*   arow = (const int*)  d_in[1];
    const int*   acol = (const int*)  d_in[2];
    const float* aval = (const float*)d_in[3];
    const float* w    = (const float*)d_in[4];
    float*       out  = (float*)d_out;

    const int n_edges = in_sizes[1];
    const int smem_bytes = (DIN * DOUT + 2 * KC * RPB) * sizeof(float);  // 96 KB

    // Idempotent attribute set (not a stream op -> capture-safe)
    cudaFuncSetAttribute(gemm_kernel, cudaFuncAttributeMaxDynamicSharedMemorySize,
                         smem_bytes);

    cudaMemsetAsync(out, 0, (size_t)out_size * sizeof(float), 0);

    gemm_kernel<<<(NN + RPB - 1) / RPB, GTHREADS, smem_bytes>>>(x, w);

    long long sthreads = (long long)n_edges * 8;
    int sblocks = (int)((sthreads + 255) / 256);
    scatter_kernel<<<sblocks, 256>>>(arow, acol, aval, out, n_edges);

    int n4 = out_size / 4;
    relu_kernel<<<(n4 + 255) / 256, 256>>>(out, n4);
}

// round 5
// speedup vs baseline: 1.0548x; 1.0548x over previous
#include <cuda_runtime.h>

// Problem constants (fixed by the dataset)
#define NN      100000      // nodes
#define DIN     256         // input feature dim
#define DOUT    32          // output feature dim
#define KC      32          // K-chunk (floats) per stage
#define NCHUNK  (DIN / KC)  // 8 chunks
#define RPB     128         // rows per GEMM block
#define GTHREADS 128

// Scratch for pre_sup = x @ W  [NN, DOUT] (12.8 MB, device global per rules)
__device__ float g_presup[(size_t)NN * DOUT];

typedef unsigned long long ull;

__device__ __forceinline__ void ffma2(ull& d, ull a, ull b) {
    asm volatile("fma.rn.f32x2 %0, %1, %2, %0;" : "+l"(d) : "l"(a), "l"(b));
}
__device__ __forceinline__ ull pack2(float x) {
    ull r; asm("mov.b64 %0, {%1, %1};" : "=l"(r) : "f"(x)); return r;
}
__device__ __forceinline__ void unpack2(ull v, float& lo, float& hi) {
    asm("mov.b64 {%0, %1}, %2;" : "=f"(lo), "=f"(hi) : "l"(v));
}

// ---------------------------------------------------------------------------
// Kernel 1: GEMM  pre_sup[N, 32] = x[N, 256] @ W[256, 32]
// 128 threads/block covering 128 rows x 32 cols. Thread tile 4 rows x 8 cols
// as 4x4 packed f32x2 accumulators (FFMA2).
// Inner loop = 3 x LDS.128 per k-iter:
//   - x: k-major tile Xs[k][row]; thread's 4 rows contiguous -> 1 LDS.128
//   - W: 8-col slice as 2 x LDS.128 (longlong2: components are packed pairs)
// vs 8 LDS/k before -> shared/MIO pipe unbound, fma pipe becomes the limiter.
// ---------------------------------------------------------------------------
__global__ __launch_bounds__(GTHREADS, 6) void gemm_kernel(const float* __restrict__ x,
                                                           const float* __restrict__ w) {
    __shared__ float Ws[KC * DOUT];      // 4 KB  (current K-chunk of W, [k][32])
    __shared__ float Xs[KC * RPB];       // 16 KB (K-MAJOR: Xs[k*RPB + row])

    const int tid  = threadIdx.x;
    const int row0 = blockIdx.x * RPB;
    const int tc   = tid & 3;    // -> cols  tc*8 .. tc*8+7
    const int tr   = tid >> 2;   // -> rows  tr*4 .. tr*4+3

    ull acc[4][4];
#pragma unroll
    for (int r = 0; r < 4; r++)
#pragma unroll
        for (int c = 0; c < 4; c++) acc[r][c] = 0ULL;

    const int  myrow = row0 + tid;       // this thread's load row
    const bool rowok = (myrow < NN);
    const float* xrow = x + (size_t)myrow * DIN;
    const float4 f0 = make_float4(0.f, 0.f, 0.f, 0.f);

    for (int kc = 0; kc < DIN; kc += KC) {
        __syncthreads();
        // Load W chunk [KC, 32] = 256 float4 across 128 threads (2 each)
        {
            const float4* wsrc = (const float4*)(w + (size_t)kc * DOUT);
            ((float4*)Ws)[tid]            = wsrc[tid];
            ((float4*)Ws)[tid + GTHREADS] = wsrc[tid + GTHREADS];
        }
        // Load X tile: thread tid owns global row (row0+tid); 8 float4 along k,
        // transpose-stored into Xs[k][tid] (bank = lane -> conflict-free).
#pragma unroll
        for (int c4 = 0; c4 < KC / 4; c4++) {
            float4 v = rowok ? *(const float4*)(xrow + kc + c4 * 4) : f0;
            Xs[(c4 * 4 + 0) * RPB + tid] = v.x;
            Xs[(c4 * 4 + 1) * RPB + tid] = v.y;
            Xs[(c4 * 4 + 2) * RPB + tid] = v.z;
            Xs[(c4 * 4 + 3) * RPB + tid] = v.w;
        }
        __syncthreads();

#pragma unroll 8
        for (int k = 0; k < KC; k++) {
            // W slice: cols tc*8..tc*8+7 as two 16B loads of packed pairs
            const longlong2 wA = *(const longlong2*)(Ws + k * DOUT + tc * 8);
            const longlong2 wB = *(const longlong2*)(Ws + k * DOUT + tc * 8 + 4);
            // x for this thread's 4 contiguous rows at this k: one 16B load
            const float4 xv = *(const float4*)(Xs + k * RPB + tr * 4);

            ull x0 = pack2(xv.x), x1 = pack2(xv.y);
            ull x2 = pack2(xv.z), x3 = pack2(xv.w);

            ffma2(acc[0][0], x0, (ull)wA.x); ffma2(acc[0][1], x0, (ull)wA.y);
            ffma2(acc[0][2], x0, (ull)wB.x); ffma2(acc[0][3], x0, (ull)wB.y);
            ffma2(acc[1][0], x1, (ull)wA.x); ffma2(acc[1][1], x1, (ull)wA.y);
            ffma2(acc[1][2], x1, (ull)wB.x); ffma2(acc[1][3], x1, (ull)wB.y);
            ffma2(acc[2][0], x2, (ull)wA.x); ffma2(acc[2][1], x2, (ull)wA.y);
            ffma2(acc[2][2], x2, (ull)wB.x); ffma2(acc[2][3], x2, (ull)wB.y);
            ffma2(acc[3][0], x3, (ull)wA.x); ffma2(acc[3][1], x3, (ull)wA.y);
            ffma2(acc[3][2], x3, (ull)wB.x); ffma2(acc[3][3], x3, (ull)wB.y);
        }
    }

    // Epilogue: unpack and store two float4 per row
#pragma unroll
    for (int r = 0; r < 4; r++) {
        int grow = row0 + tr * 4 + r;
        if (grow < NN) {
            float4 o0, o1;
            unpack2(acc[r][0], o0.x, o0.y);
            unpack2(acc[r][1], o0.z, o0.w);
            unpack2(acc[r][2], o1.x, o1.y);
            unpack2(acc[r][3], o1.z, o1.w);
            float* dst = g_presup + (size_t)grow * DOUT + tc * 8;
            *(float4*)(dst + 0) = o0;
            *(float4*)(dst + 4) = o1;
        }
    }
}

// ---------------------------------------------------------------------------
// Kernel 2: Scatter SpMM  out[row[e]] += val[e] * pre_sup[col[e]]
// 8 threads per edge; one float4 gather + one red.global.add.v4.f32 each.
// ---------------------------------------------------------------------------
__global__ __launch_bounds__(256) void scatter_kernel(const int*   __restrict__ arow,
                                                      const int*   __restrict__ acol,
                                                      const float* __restrict__ aval,
                                                      float*       __restrict__ out,
                                                      int n_edges) {
    long long g = (long long)blockIdx.x * blockDim.x + threadIdx.x;
    int e    = (int)(g >> 3);
    int part = (int)(g & 7);
    if (e >= n_edges) return;

    int   r = arow[e];
    int   c = acol[e];
    float v = aval[e];

    float4 p = *(const float4*)(g_presup + (size_t)c * DOUT + part * 4);
    float m0 = v * p.x, m1 = v * p.y, m2 = v * p.z, m3 = v * p.w;

    float* dst = out + (size_t)r * DOUT + part * 4;
    asm volatile("red.global.add.v4.f32 [%0], {%1, %2, %3, %4};"
                 :: "l"(dst), "f"(m0), "f"(m1), "f"(m2), "f"(m3)
                 : "memory");
}

// ---------------------------------------------------------------------------
// Kernel 3: in-place ReLU on out
// ---------------------------------------------------------------------------
__global__ __launch_bounds__(256) void relu_kernel(float* __restrict__ out, int n4) {
    int i = blockIdx.x * blockDim.x + threadIdx.x;
    if (i < n4) {
        float4 v = ((float4*)out)[i];
        v.x = fmaxf(v.x, 0.f);
        v.y = fmaxf(v.y, 0.f);
        v.z = fmaxf(v.z, 0.f);
        v.w = fmaxf(v.w, 0.f);
        ((float4*)out)[i] = v;
    }
}

// ---------------------------------------------------------------------------
// kernel_launch: memset(out) -> gemm -> scatter -> relu
// ---------------------------------------------------------------------------
extern "C" void kernel_launch(void* const* d_in, const int* in_sizes, int n_in,
                              void* d_out, int out_size) {
    const float* x    = (const float*)d_in[0];
    const int*   arow = (const int*)  d_in[1];
    const int*   acol = (const int*)  d_in[2];
    const float* aval = (const float*)d_in[3];
    const float* w    = (const float*)d_in[4];
    float*       out  = (float*)d_out;

    const int n_edges = in_sizes[1];

    cudaMemsetAsync(out, 0, (size_t)out_size * sizeof(float), 0);

    gemm_kernel<<<(NN + RPB - 1) / RPB, GTHREADS>>>(x, w);

    long long sthreads = (long long)n_edges * 8;
    int sblocks = (int)((sthreads + 255) / 256);
    scatter_kernel<<<sblocks, 256>>>(arow, acol, aval, out, n_edges);

    int n4 = out_size / 4;
    relu_kernel<<<(n4 + 255) / 256, 256>>>(out, n4);
}